// round 7
// baseline (speedup 1.0000x reference)
#include <cuda_runtime.h>
#include <math.h>
#include <stdint.h>

#define NN 8192
#define KK 32
#define NT 64                       // 8192/128 tiles per dim
#define NOFF (NT*(NT-1)/2)          // 2016 strictly-upper tiles
#define NTILES (NOFF + NT)          // 2080 tiles total
#define NSM 148                     // persistent grid

typedef unsigned long long u64;

#define FMA2(d,a,b,c) asm("fma.rn.f32x2 %0, %1, %2, %3;" : "=l"(d) : "l"(a), "l"(b), "l"(c))
#define PK2(d,lo,hi)  asm("mov.b64 %0, {%1, %2};" : "=l"(d) : "f"(lo), "f"(hi))
#define UPK2(lo,hi,s) asm("mov.b64 {%0, %1}, %2;" : "=f"(lo), "=f"(hi) : "l"(s))
#define CPA16(dst,src) asm volatile("cp.async.cg.shared.global [%0], [%1], 16;" :: "r"(dst), "l"(src))
#define CPCOMMIT()     asm volatile("cp.async.commit_group;" ::: "memory")
#define CPWAIT1()      asm volatile("cp.async.wait_group 1;" ::: "memory")

// dynamic smem layout (bytes)
#define SM_D0   0                   // dir buf 0: 128 rows x 512B, XOR-swizzled   65536
#define SM_D1   65536               // dir buf 1                                   65536
#define SM_XT   131072              // Xt[32][128]                                 16384
#define SM_YT   147456              // Yt[32][128]                                 16384
#define SM_BI   163840              // 512
#define SM_BJ   164352              // 512
#define SM_RED  164864              // 32 floats
#define PAIR_SMEM 164992

// ---- scratch (no allocations allowed) ----
__device__ float  d_Wpart[64*KK*KK];
__device__ float  d_Spart[64*KK];
__device__ float  d_M [KK*KK];
__device__ float  d_Ya[KK*NN];          // 2a * M @ X
__device__ float  d_bv[NN];             // beta - a*q
__device__ double d_partSP[NTILES];
__device__ double d_partTA[NTILES];

// ---------- fused prep: softmax(X) chunk + exp(C) chunk + partial W,S ----------
__global__ void k_prep(const float* __restrict__ X, const float* __restrict__ C) {
    __shared__ float xs[KK][132];
    __shared__ float ec[KK][132];
    int blk = blockIdx.x, tid = threadIdx.x;
    int base = blk * 128;

    if (tid < 128) {
        int i = base + tid;
        float v[KK]; float s = 0.f;
#pragma unroll
        for (int p = 0; p < KK; p++) { v[p] = __expf(X[p*NN + i]); s += v[p]; }
        float inv = 1.f / s;
#pragma unroll
        for (int p = 0; p < KK; p++) xs[p][tid] = v[p] * inv;
    } else {
        int r = tid - 128;
        const float4* cp = (const float4*)&C[(base + r)*KK];
#pragma unroll
        for (int c4 = 0; c4 < 8; c4++) {
            float4 v = cp[c4];
            ec[c4*4+0][r] = __expf(v.x);
            ec[c4*4+1][r] = __expf(v.y);
            ec[c4*4+2][r] = __expf(v.z);
            ec[c4*4+3][r] = __expf(v.w);
        }
    }
    __syncthreads();

    if (tid < 32) {
        float s = 0.f;
#pragma unroll 8
        for (int r = 0; r < 128; r++) s += ec[tid][r];
        d_Spart[blk*32 + tid] = s;
    }

    int p = tid >> 3, k0 = (tid & 7) * 4;
    float a0 = 0.f, a1 = 0.f, a2 = 0.f, a3 = 0.f;
#pragma unroll 4
    for (int ii = 0; ii < 128; ii++) {
        float xv = xs[p][ii];
        a0 += xv * ec[k0+0][ii];
        a1 += xv * ec[k0+1][ii];
        a2 += xv * ec[k0+2][ii];
        a3 += xv * ec[k0+3][ii];
    }
    float* out = &d_Wpart[blk*1024 + p*32 + k0];
    out[0] = a0; out[1] = a1; out[2] = a2; out[3] = a3;
}

// ---------- fused: reduce partials, E = W/S, M = E^T E ----------
__global__ void k_wredM() {
    __shared__ float Es[KK*KK];
    __shared__ float Ssm[KK];
    int tid = threadIdx.x;
    float w[4];
#pragma unroll
    for (int c = 0; c < 4; c++) {
        int e = tid*4 + c;
        float s = 0.f;
#pragma unroll 8
        for (int b = 0; b < 64; b++) s += d_Wpart[b*1024 + e];
        w[c] = s;
    }
    if (tid < 32) {
        float s = 0.f;
#pragma unroll 8
        for (int b = 0; b < 64; b++) s += d_Spart[b*32 + tid];
        Ssm[tid] = s;
    }
    __syncthreads();
#pragma unroll
    for (int c = 0; c < 4; c++) {
        int e = tid*4 + c;
        Es[e] = w[c] / Ssm[e & 31];
    }
    __syncthreads();
#pragma unroll
    for (int c = 0; c < 4; c++) {
        int e = tid*4 + c;
        int p = e >> 5, q = e & 31;
        float s = 0.f;
#pragma unroll
        for (int r = 0; r < KK; r++) s += Es[r*KK + p] * Es[r*KK + q];
        d_M[e] = s;
    }
}

// ---------- Ya = 2a*M*X, b = beta - a*q ----------
__global__ void k_ya(const float* __restrict__ X, const float* __restrict__ beta,
                     const float* __restrict__ a_p) {
    __shared__ __align__(16) float Ms[KK][KK];
    __shared__ float Xw[KK][33];
    __shared__ float qsm[8][32];
    int tid = threadIdx.x;
    int lane = tid & 31, w = tid >> 5;
    int cbase = blockIdx.x * 32;

#pragma unroll
    for (int c = 0; c < 4; c++) {
        int idx = c*256 + tid;
        Ms[idx >> 5][idx & 31] = d_M[idx];
    }
#pragma unroll
    for (int c = 0; c < 4; c++) {
        int idx = c*256 + tid;
        int q = idx >> 5, col = idx & 31;
        Xw[q][col] = X[q*NN + cbase + col];
    }
    __syncthreads();

    float a = a_p[0];
    float twoa = 2.f * a;
    float xv[KK];
#pragma unroll
    for (int q = 0; q < KK; q++) xv[q] = Xw[q][lane];

    int i = cbase + lane;
    float qp = 0.f;
#pragma unroll
    for (int pp = 0; pp < 4; pp++) {
        int p = w*4 + pp;
        const float4* mrow = (const float4*)&Ms[p][0];
        float tp = 0.f;
#pragma unroll
        for (int q4 = 0; q4 < 8; q4++) {
            float4 m = mrow[q4];
            tp += m.x * xv[q4*4+0] + m.y * xv[q4*4+1]
                + m.z * xv[q4*4+2] + m.w * xv[q4*4+3];
        }
        d_Ya[p*NN + i] = twoa * tp;
        qp += xv[p] * tp;
    }
    qsm[w][lane] = qp;
    __syncthreads();
    if (w == 0) {
        float qf = 0.f;
#pragma unroll
        for (int ww = 0; ww < 8; ww++) qf += qsm[ww][lane];
        d_bv[i] = beta[i] - a * qf;
    }
}

__device__ __forceinline__ float softplusf(float x) {
    return fmaxf(x, 0.f) + __logf(1.f + __expf(-fabsf(x)));
}

__device__ __forceinline__ void tile_IJ(int pid, int& I, int& J) {
    if (pid < NOFF) {
        int rem = pid, rl = NT - 1; I = 0;
        while (rem >= rl) { rem -= rl; rl--; I++; }
        J = I + 1 + rem;
    } else {
        I = pid - NOFF; J = I;
    }
}

// issue one 128x128 dir A-block via cp.async into an XOR-swizzled buffer
__device__ __forceinline__ void issue_dir(const float* __restrict__ A,
                                          int iB, int jB, uint32_t dbase, int tid) {
#pragma unroll
    for (int c = 0; c < 8; c++) {
        int idx = c*512 + tid;
        int row = idx >> 5, c16 = idx & 31;
        int sw = c16 ^ (row & 31);
        CPA16(dbase + row*512 + sw*16, &A[(u64)(iB + row)*NN + jB + c16*4]);
    }
    CPCOMMIT();
}

// ---------- persistent pair kernel ----------
__global__ void __launch_bounds__(512, 1)
k_pairs(const float* __restrict__ X, const float* __restrict__ A) {
    extern __shared__ char sm[];
    float (*Xt)[128] = (float(*)[128])(sm + SM_XT);
    float (*Yt)[128] = (float(*)[128])(sm + SM_YT);
    float* bI  = (float*)(sm + SM_BI);
    float* bJ  = (float*)(sm + SM_BJ);
    float* red = (float*)(sm + SM_RED);

    int tid = threadIdx.x, bid = blockIdx.x;
    int tx = tid & 15, ty = tid >> 4;          // cols tx*4 / 64+tx*4 ; rows ty*4..+4
    uint32_t dB[2];
    dB[0] = (uint32_t)__cvta_generic_to_shared(sm + SM_D0);
    dB[1] = (uint32_t)__cvta_generic_to_shared(sm + SM_D1);

    // ---- prologue: prefetch dir for first two tiles ----
    {
        int I, J;
        tile_IJ(bid, I, J);
        issue_dir(A, I*128, J*128, dB[0], tid);
        if (bid + NSM < NTILES) {
            tile_IJ(bid + NSM, I, J);
            issue_dir(A, I*128, J*128, dB[1], tid);
        } else CPCOMMIT();
    }

    int nbuf = 0;
    for (int T = bid; T < NTILES; T += NSM, nbuf ^= 1) {
        int I, J;
        tile_IJ(T, I, J);
        bool isDiag = (I == J);
        int iBase = I * 128, jBase = J * 128;

        // ---- 1. stage X/Ya tiles + biases (L2-resident) ----
#pragma unroll
        for (int c = 0; c < 2; c++) {
            int e = c*2048 + tid*4;
            int p = e >> 7, ii = e & 127;
            *(float4*)&Xt[p][ii] = *(const float4*)&X   [p*NN + iBase + ii];
            *(float4*)&Yt[p][ii] = *(const float4*)&d_Ya[p*NN + jBase + ii];
        }
        if (tid < 128) bI[tid] = d_bv[iBase + tid];
        else if (tid < 256) bJ[tid - 128] = d_bv[jBase + tid - 128];
        __syncthreads();

        // ---- 2. theta mainloop (FFMA2), dir(T+1) streaming underneath ----
        float bIr[4], bJc[8];
#pragma unroll
        for (int r = 0; r < 4; r++) bIr[r] = bI[ty*4 + r];
#pragma unroll
        for (int c = 0; c < 4; c++) { bJc[c] = bJ[tx*4 + c]; bJc[c+4] = bJ[64 + tx*4 + c]; }

        u64 acc2[4][4];
#pragma unroll
        for (int r = 0; r < 4; r++)
#pragma unroll
            for (int cp = 0; cp < 4; cp++)
                PK2(acc2[r][cp], bIr[r] + bJc[2*cp], bIr[r] + bJc[2*cp + 1]);

#pragma unroll
        for (int k = 0; k < KK; k++) {
            float4 xa = *(float4*)&Xt[k][ty*4];
            float4 ya = *(float4*)&Yt[k][tx*4];
            float4 yb = *(float4*)&Yt[k][64 + tx*4];
            u64 y2[4];
            PK2(y2[0], ya.x, ya.y); PK2(y2[1], ya.z, ya.w);
            PK2(y2[2], yb.x, yb.y); PK2(y2[3], yb.z, yb.w);
            float xf[4] = {xa.x, xa.y, xa.z, xa.w};
#pragma unroll
            for (int r = 0; r < 4; r++) {
                u64 xx;
                PK2(xx, xf[r], xf[r]);
#pragma unroll
                for (int cp = 0; cp < 4; cp++)
                    FMA2(acc2[r][cp], xx, y2[cp], acc2[r][cp]);
            }
        }

        // ---- 3. issue transposed-A LDGs early (latency hidden by softplus) ----
        float4 trp[8];
        if (!isDiag) {
#pragma unroll
            for (int c = 0; c < 8; c++) {
                int j = (c < 4) ? (tx*4 + c) : (64 + tx*4 + (c - 4));
                trp[c] = __ldcs((const float4*)&A[(u64)(jBase + j)*NN + iBase + ty*4]);
            }
        }

        // ---- 4. softplus (MUFU) ----
        float sSP = 0.f;
        if (!isDiag) {
#pragma unroll
            for (int r = 0; r < 4; r++)
#pragma unroll
                for (int cp = 0; cp < 4; cp++) {
                    float t0, t1;
                    UPK2(t0, t1, acc2[r][cp]);
                    sSP += softplusf(t0) + softplusf(t1);
                }
            sSP *= 2.f;
        } else {
#pragma unroll
            for (int r = 0; r < 4; r++) {
                int gi = ty*4 + r;
#pragma unroll
                for (int c = 0; c < 8; c++) {
                    int gj = (c < 4) ? (tx*4 + c) : (64 + tx*4 + (c - 4));
                    float t0, t1;
                    UPK2(t0, t1, acc2[r][c >> 1]);
                    float th = (c & 1) ? t1 : t0;
                    if (gi < gj) sSP += 2.f * softplusf(th);
                }
            }
        }

        // ---- 5. consume transposed A (registers) ----
        float sTA = 0.f;
        if (!isDiag) {
#pragma unroll
            for (int c = 0; c < 8; c++) {
                float atv[4] = {trp[c].x, trp[c].y, trp[c].z, trp[c].w};
                int cp = c >> 1;
#pragma unroll
                for (int r = 0; r < 4; r++) {
                    float t0, t1;
                    UPK2(t0, t1, acc2[r][cp]);
                    sTA += ((c & 1) ? t1 : t0) * atv[r];
                }
            }
        }

        // ---- 6. wait for dir(T), consume from smem ----
        CPWAIT1();
        __syncthreads();

        const float* dbuf = (const float*)(sm + (nbuf ? SM_D1 : SM_D0));
        u64 sTA2; PK2(sTA2, 0.f, 0.f);
#pragma unroll
        for (int r = 0; r < 4; r++) {
            int row = ty*4 + r;
            int sw0 = (tx      ^ (row & 31));
            int sw1 = ((16+tx) ^ (row & 31));
            float4 a0 = *(const float4*)&dbuf[row*128 + sw0*4];
            float4 a1 = *(const float4*)&dbuf[row*128 + sw1*4];
            u64 a2[4];
            PK2(a2[0], a0.x, a0.y); PK2(a2[1], a0.z, a0.w);
            PK2(a2[2], a1.x, a1.y); PK2(a2[3], a1.z, a1.w);
#pragma unroll
            for (int cp = 0; cp < 4; cp++)
                FMA2(sTA2, acc2[r][cp], a2[cp], sTA2);
        }
        {
            float t0, t1;
            UPK2(t0, t1, sTA2);
            sTA += t0 + t1;
        }

        // ---- 7. reissue this buffer for tile T+2*NSM ----
        __syncthreads();
        {
            int Tn = T + 2*NSM;
            if (Tn < NTILES) {
                int In, Jn;
                tile_IJ(Tn, In, Jn);
                issue_dir(A, In*128, Jn*128, dB[nbuf], tid);
            } else CPCOMMIT();
        }

        // ---- 8. deterministic reduction + store ----
#pragma unroll
        for (int o = 16; o > 0; o >>= 1) {
            sSP += __shfl_xor_sync(0xffffffffu, sSP, o);
            sTA += __shfl_xor_sync(0xffffffffu, sTA, o);
        }
        int wid = tid >> 5, lane = tid & 31;
        if (lane == 0) { red[wid] = sSP; red[16 + wid] = sTA; }
        __syncthreads();
        if (tid == 0) {
            float s1 = 0.f, s2 = 0.f;
#pragma unroll
            for (int w = 0; w < 16; w++) { s1 += red[w]; s2 += red[16 + w]; }
            d_partSP[T] = (double)s1;
            d_partTA[T] = (double)s2;
        }
        __syncthreads();
    }
}

// ---------- deterministic final reduction ----------
__global__ void k_final(float* __restrict__ out) {
    __shared__ double rSP[256], rTA[256];
    int t = threadIdx.x;
    double s1 = 0.0, s2 = 0.0;
    for (int i = t; i < NTILES; i += 256) { s1 += d_partSP[i]; s2 += d_partTA[i]; }
    rSP[t] = s1; rTA[t] = s2; __syncthreads();
    for (int s = 128; s > 0; s >>= 1) {
        if (t < s) { rSP[t] += rSP[t+s]; rTA[t] += rTA[t+s]; }
        __syncthreads();
    }
    if (t == 0) out[0] = (float)(0.5 * rTA[0] - 0.5 * rSP[0]);
}

extern "C" void kernel_launch(void* const* d_in, const int* in_sizes, int n_in,
                              void* d_out, int out_size) {
    const float* A    = (const float*)d_in[0];
    const float* beta = (const float*)d_in[1];
    const float* a    = (const float*)d_in[2];
    const float* X    = (const float*)d_in[3];
    const float* C    = (const float*)d_in[4];
    float* out = (float*)d_out;

    cudaFuncSetAttribute(k_pairs, cudaFuncAttributeMaxDynamicSharedMemorySize, PAIR_SMEM);

    k_prep<<<64, 256>>>(X, C);                       // 1
    k_wredM<<<1, 256>>>();                           // 2
    k_ya<<<NN/32, 256>>>(X, beta, a);                // 3
    k_pairs<<<NSM, 512, PAIR_SMEM>>>(X, A);          // 4  <- profiled slot
    k_final<<<1, 256>>>(out);                        // 5
}

// round 8
// speedup vs baseline: 1.1762x; 1.1762x over previous
#include <cuda_runtime.h>
#include <math.h>
#include <stdint.h>

#define NN 8192
#define KK 32
#define NT 64                       // 8192/128 tiles per dim
#define NOFF (NT*(NT-1)/2)          // 2016 strictly-upper tiles
#define NTILES (NOFF + NT)          // 2080 tiles

typedef unsigned long long u64;

#define FMA2(d,a,b,c) asm("fma.rn.f32x2 %0, %1, %2, %3;" : "=l"(d) : "l"(a), "l"(b), "l"(c))
#define PK2(d,lo,hi)  asm("mov.b64 %0, {%1, %2};" : "=l"(d) : "f"(lo), "f"(hi))
#define UPK2(lo,hi,s) asm("mov.b64 {%0, %1}, %2;" : "=f"(lo), "=f"(hi) : "l"(s))
#define CPA16(dst,src) asm volatile("cp.async.cg.shared.global [%0], [%1], 16;" :: "r"(dst), "l"(src))

// dynamic smem layout (bytes): Xt 16K | Yt 16K | Adir 64K (XOR-swizzled) | bI | bJ | red
#define SM_XT   0
#define SM_YT   16384
#define SM_ADIR 32768
#define SM_BI   98304
#define SM_BJ   98816
#define SM_RED  99328
#define PAIR_SMEM 99392

// ---- scratch (no allocations allowed) ----
__device__ float  d_Wpart[64*KK*KK];
__device__ float  d_Spart[64*KK];
__device__ float  d_M [KK*KK];
__device__ float  d_Ya[KK*NN];          // 2a * M @ X
__device__ float  d_bv[NN];             // beta - a*q
__device__ double d_partSP[NTILES];
__device__ double d_partTA[NTILES];

// ---------- fused prep: softmax(X) chunk + exp(C) chunk + partial W,S ----------
__global__ void k_prep(const float* __restrict__ X, const float* __restrict__ C) {
    __shared__ float xs[KK][132];
    __shared__ float ec[KK][132];
    int blk = blockIdx.x, tid = threadIdx.x;
    int base = blk * 128;

    if (tid < 128) {
        int i = base + tid;
        float v[KK]; float s = 0.f;
#pragma unroll
        for (int p = 0; p < KK; p++) { v[p] = __expf(X[p*NN + i]); s += v[p]; }
        float inv = 1.f / s;
#pragma unroll
        for (int p = 0; p < KK; p++) xs[p][tid] = v[p] * inv;
    } else {
        int r = tid - 128;
        const float4* cp = (const float4*)&C[(base + r)*KK];
#pragma unroll
        for (int c4 = 0; c4 < 8; c4++) {
            float4 v = cp[c4];
            ec[c4*4+0][r] = __expf(v.x);
            ec[c4*4+1][r] = __expf(v.y);
            ec[c4*4+2][r] = __expf(v.z);
            ec[c4*4+3][r] = __expf(v.w);
        }
    }
    __syncthreads();

    if (tid < 32) {
        float s = 0.f;
#pragma unroll 8
        for (int r = 0; r < 128; r++) s += ec[tid][r];
        d_Spart[blk*32 + tid] = s;
    }

    int p = tid >> 3, k0 = (tid & 7) * 4;
    float a0 = 0.f, a1 = 0.f, a2 = 0.f, a3 = 0.f;
#pragma unroll 4
    for (int ii = 0; ii < 128; ii++) {
        float xv = xs[p][ii];
        a0 += xv * ec[k0+0][ii];
        a1 += xv * ec[k0+1][ii];
        a2 += xv * ec[k0+2][ii];
        a3 += xv * ec[k0+3][ii];
    }
    float* out = &d_Wpart[blk*1024 + p*32 + k0];
    out[0] = a0; out[1] = a1; out[2] = a2; out[3] = a3;
}

// ---------- fused: reduce partials, E = W/S, M = E^T E ----------
__global__ void k_wredM() {
    __shared__ float Es[KK*KK];
    __shared__ float Ssm[KK];
    int tid = threadIdx.x;
    float w[4];
#pragma unroll
    for (int c = 0; c < 4; c++) {
        int e = tid*4 + c;
        float s = 0.f;
#pragma unroll 8
        for (int b = 0; b < 64; b++) s += d_Wpart[b*1024 + e];
        w[c] = s;
    }
    if (tid < 32) {
        float s = 0.f;
#pragma unroll 8
        for (int b = 0; b < 64; b++) s += d_Spart[b*32 + tid];
        Ssm[tid] = s;
    }
    __syncthreads();
#pragma unroll
    for (int c = 0; c < 4; c++) {
        int e = tid*4 + c;
        Es[e] = w[c] / Ssm[e & 31];
    }
    __syncthreads();
#pragma unroll
    for (int c = 0; c < 4; c++) {
        int e = tid*4 + c;
        int p = e >> 5, q = e & 31;
        float s = 0.f;
#pragma unroll
        for (int r = 0; r < KK; r++) s += Es[r*KK + p] * Es[r*KK + q];
        d_M[e] = s;
    }
}

// ---------- Ya = 2a*M*X, b = beta - a*q ----------
__global__ void k_ya(const float* __restrict__ X, const float* __restrict__ beta,
                     const float* __restrict__ a_p) {
    __shared__ __align__(16) float Ms[KK][KK];
    __shared__ float Xw[KK][33];
    __shared__ float qsm[8][32];
    int tid = threadIdx.x;
    int lane = tid & 31, w = tid >> 5;
    int cbase = blockIdx.x * 32;

    // issue X loads first (independent), then M — maximize MLP
    float xstage;
    {
        int idx0 = tid;                    // covers 256 of 1024
        int q = idx0 >> 5, col = idx0 & 31;
        xstage = X[q*NN + cbase + col];
    }
#pragma unroll
    for (int c = 1; c < 4; c++) {
        int idx = c*256 + tid;
        int q = idx >> 5, col = idx & 31;
        Xw[q][col] = X[q*NN + cbase + col];
    }
    {
        int q = tid >> 5, col = tid & 31;
        Xw[q][col] = xstage;
    }
#pragma unroll
    for (int c = 0; c < 4; c++) {
        int idx = c*256 + tid;
        Ms[idx >> 5][idx & 31] = d_M[idx];
    }
    __syncthreads();

    float a = a_p[0];
    float twoa = 2.f * a;
    float xv[KK];
#pragma unroll
    for (int q = 0; q < KK; q++) xv[q] = Xw[q][lane];

    int i = cbase + lane;
    float qp = 0.f;
#pragma unroll
    for (int pp = 0; pp < 4; pp++) {
        int p = w*4 + pp;
        const float4* mrow = (const float4*)&Ms[p][0];
        float tp = 0.f;
#pragma unroll
        for (int q4 = 0; q4 < 8; q4++) {
            float4 m = mrow[q4];
            tp += m.x * xv[q4*4+0] + m.y * xv[q4*4+1]
                + m.z * xv[q4*4+2] + m.w * xv[q4*4+3];
        }
        d_Ya[p*NN + i] = twoa * tp;
        qp += xv[p] * tp;
    }
    qsm[w][lane] = qp;
    __syncthreads();
    if (w == 0) {
        float qf = 0.f;
#pragma unroll
        for (int ww = 0; ww < 8; ww++) qf += qsm[ww][lane];
        d_bv[i] = beta[i] - a * qf;
    }
}

__device__ __forceinline__ float softplusf(float x) {
    return fmaxf(x, 0.f) + __logf(1.f + __expf(-fabsf(x)));
}

// ---------- pair kernel: one 128x128 tile per block ----------
__global__ void __launch_bounds__(256, 2)
k_pairs(const float* __restrict__ X, const float* __restrict__ A) {
    extern __shared__ char sm[];
    float (*Xt)[128] = (float(*)[128])(sm + SM_XT);
    float (*Yt)[128] = (float(*)[128])(sm + SM_YT);
    float* bI  = (float*)(sm + SM_BI);
    float* bJ  = (float*)(sm + SM_BJ);
    float* red = (float*)(sm + SM_RED);

    int pid = blockIdx.x, tid = threadIdx.x;
    int I, J;
    if (pid < NOFF) {
        int rem = pid, rl = NT - 1; I = 0;
        while (rem >= rl) { rem -= rl; rl--; I++; }
        J = I + 1 + rem;
    } else {
        I = pid - NOFF; J = I;
    }
    bool isDiag = (I == J);
    int iBase = I * 128, jBase = J * 128;

    // ---- 1. start dir A block via cp.async, XOR-swizzled (overlaps mainloop) ----
    {
        uint32_t adir = (uint32_t)__cvta_generic_to_shared(sm + SM_ADIR);
#pragma unroll
        for (int c = 0; c < 16; c++) {
            int idx = c*256 + tid;
            int row = idx >> 5, c16 = idx & 31;
            int sw = c16 ^ (row & 31);
            CPA16(adir + row*512 + sw*16, &A[(u64)(iBase + row)*NN + jBase + c16*4]);
        }
        asm volatile("cp.async.commit_group;" ::: "memory");
    }

    // ---- 2. stage X/Ya tiles + biases ----
#pragma unroll
    for (int c = 0; c < 4; c++) {
        int e = c*1024 + tid*4;
        int p = e >> 7, ii = e & 127;
        *(float4*)&Xt[p][ii] = *(const float4*)&X   [p*NN + iBase + ii];
        *(float4*)&Yt[p][ii] = *(const float4*)&d_Ya[p*NN + jBase + ii];
    }
    if (tid < 128) bI[tid] = d_bv[iBase + tid];
    else           bJ[tid - 128] = d_bv[jBase + tid - 128];
    __syncthreads();

    int tx = tid & 15, ty = tid >> 4;
    float bIr[8], bJc[8];
#pragma unroll
    for (int r = 0; r < 8; r++) bIr[r] = bI[ty*8 + r];
#pragma unroll
    for (int c = 0; c < 4; c++) { bJc[c] = bJ[tx*4 + c]; bJc[c+4] = bJ[64 + tx*4 + c]; }

    u64 acc2[8][4];
#pragma unroll
    for (int r = 0; r < 8; r++)
#pragma unroll
        for (int cp = 0; cp < 4; cp++)
            PK2(acc2[r][cp], bIr[r] + bJc[2*cp], bIr[r] + bJc[2*cp + 1]);

    // ---- 3. FFMA2 mainloop (dir A-stream arrives underneath) ----
#pragma unroll
    for (int k = 0; k < KK; k++) {
        float4 xa = *(float4*)&Xt[k][ty*8];
        float4 xb = *(float4*)&Xt[k][ty*8 + 4];
        const u64* yp0 = (const u64*)&Yt[k][tx*4];
        const u64* yp1 = (const u64*)&Yt[k][64 + tx*4];
        u64 y2[4] = {yp0[0], yp0[1], yp1[0], yp1[1]};
        float xf[8] = {xa.x, xa.y, xa.z, xa.w, xb.x, xb.y, xb.z, xb.w};
#pragma unroll
        for (int r = 0; r < 8; r++) {
            u64 xx;
            PK2(xx, xf[r], xf[r]);
#pragma unroll
            for (int cp = 0; cp < 4; cp++)
                FMA2(acc2[r][cp], xx, y2[cp], acc2[r][cp]);
        }
    }
    // acc2 holds theta

    // ---- 4. issue trp LDG batch 1 (cols 0..3), latency hidden by softplus ----
    float4 trp[8];   // [c][r0..3], [c][r4..7] pairs: trp[2c], trp[2c+1]
    if (!isDiag) {
#pragma unroll
        for (int c = 0; c < 4; c++) {
            int gj = jBase + tx*4 + c;
            trp[2*c  ] = __ldcs((const float4*)&A[(u64)gj*NN + iBase + ty*8]);
            trp[2*c+1] = __ldcs((const float4*)&A[(u64)gj*NN + iBase + ty*8 + 4]);
        }
    }

    // ---- 5. softplus (MUFU; overlaps trp DRAM latency) ----
    float sSP = 0.f;
    if (!isDiag) {
#pragma unroll
        for (int r = 0; r < 8; r++)
#pragma unroll
            for (int cp = 0; cp < 4; cp++) {
                float t0, t1;
                UPK2(t0, t1, acc2[r][cp]);
                sSP += softplusf(t0) + softplusf(t1);
            }
        sSP *= 2.f;
    } else {
#pragma unroll
        for (int r = 0; r < 8; r++) {
            int gi = ty*8 + r;
#pragma unroll
            for (int c = 0; c < 8; c++) {
                int gj = (c < 4) ? (tx*4 + c) : (64 + tx*4 + (c - 4));
                float t0, t1;
                UPK2(t0, t1, acc2[r][c >> 1]);
                float th = (c & 1) ? t1 : t0;
                if (gi < gj) sSP += 2.f * softplusf(th);
            }
        }
    }

    float sTA = 0.f;
    // ---- 6. consume trp batch 1; issue batch 2 (cols 4..7 -> 64+tx*4+c) ----
    if (!isDiag) {
        float4 nxt[8];
#pragma unroll
        for (int c = 0; c < 4; c++) {
            int gj = jBase + 64 + tx*4 + c;
            nxt[2*c  ] = __ldcs((const float4*)&A[(u64)gj*NN + iBase + ty*8]);
            nxt[2*c+1] = __ldcs((const float4*)&A[(u64)gj*NN + iBase + ty*8 + 4]);
        }
#pragma unroll
        for (int c = 0; c < 4; c++) {
            float atv[8] = {trp[2*c].x, trp[2*c].y, trp[2*c].z, trp[2*c].w,
                            trp[2*c+1].x, trp[2*c+1].y, trp[2*c+1].z, trp[2*c+1].w};
            int cp = c >> 1;
#pragma unroll
            for (int r = 0; r < 8; r++) {
                float t0, t1;
                UPK2(t0, t1, acc2[r][cp]);
                sTA += ((c & 1) ? t1 : t0) * atv[r];
            }
        }
#pragma unroll
        for (int c = 0; c < 8; c++) trp[c] = nxt[c];
    }

    // ---- 7. wait dir, consume from smem (hides trp batch-2 latency) ----
    asm volatile("cp.async.wait_group 0;" ::: "memory");
    __syncthreads();
    {
        const float* dbuf = (const float*)(sm + SM_ADIR);
        u64 sTA2; PK2(sTA2, 0.f, 0.f);
#pragma unroll
        for (int r = 0; r < 8; r++) {
            int row = ty*8 + r;
            int sw0 = tx ^ (row & 31);
            int sw1 = (16 + tx) ^ (row & 31);
            float4 a0 = *(const float4*)&dbuf[row*128 + sw0*4];
            float4 a1 = *(const float4*)&dbuf[row*128 + sw1*4];
            u64 a2[4];
            PK2(a2[0], a0.x, a0.y); PK2(a2[1], a0.z, a0.w);
            PK2(a2[2], a1.x, a1.y); PK2(a2[3], a1.z, a1.w);
#pragma unroll
            for (int cp = 0; cp < 4; cp++)
                FMA2(sTA2, acc2[r][cp], a2[cp], sTA2);
        }
        float t0, t1;
        UPK2(t0, t1, sTA2);
        sTA += t0 + t1;     // diag: full-block sum == sum_{i<j} th*(Aij+Aji) + diag terms
    }

    // ---- 8. consume trp batch 2 ----
    if (!isDiag) {
#pragma unroll
        for (int c = 0; c < 4; c++) {
            float atv[8] = {trp[2*c].x, trp[2*c].y, trp[2*c].z, trp[2*c].w,
                            trp[2*c+1].x, trp[2*c+1].y, trp[2*c+1].z, trp[2*c+1].w};
            int cp = 2 + (c >> 1);
#pragma unroll
            for (int r = 0; r < 8; r++) {
                float t0, t1;
                UPK2(t0, t1, acc2[r][cp]);
                sTA += ((c & 1) ? t1 : t0) * atv[r];
            }
        }
    }

    // ---- 9. deterministic reduction ----
#pragma unroll
    for (int o = 16; o > 0; o >>= 1) {
        sSP += __shfl_xor_sync(0xffffffffu, sSP, o);
        sTA += __shfl_xor_sync(0xffffffffu, sTA, o);
    }
    int wid = tid >> 5, lane = tid & 31;
    if (lane == 0) { red[wid] = sSP; red[8 + wid] = sTA; }
    __syncthreads();
    if (tid == 0) {
        float s1 = 0.f, s2 = 0.f;
#pragma unroll
        for (int w = 0; w < 8; w++) { s1 += red[w]; s2 += red[8 + w]; }
        d_partSP[pid] = (double)s1;
        d_partTA[pid] = (double)s2;
    }
}

// ---------- deterministic final reduction ----------
__global__ void k_final(float* __restrict__ out) {
    __shared__ double rSP[256], rTA[256];
    int t = threadIdx.x;
    double s1 = 0.0, s2 = 0.0;
    for (int i = t; i < NTILES; i += 256) { s1 += d_partSP[i]; s2 += d_partTA[i]; }
    rSP[t] = s1; rTA[t] = s2; __syncthreads();
    for (int s = 128; s > 0; s >>= 1) {
        if (t < s) { rSP[t] += rSP[t+s]; rTA[t] += rTA[t+s]; }
        __syncthreads();
    }
    if (t == 0) out[0] = (float)(0.5 * rTA[0] - 0.5 * rSP[0]);
}

extern "C" void kernel_launch(void* const* d_in, const int* in_sizes, int n_in,
                              void* d_out, int out_size) {
    const float* A    = (const float*)d_in[0];
    const float* beta = (const float*)d_in[1];
    const float* a    = (const float*)d_in[2];
    const float* X    = (const float*)d_in[3];
    const float* C    = (const float*)d_in[4];
    float* out = (float*)d_out;

    cudaFuncSetAttribute(k_pairs, cudaFuncAttributeMaxDynamicSharedMemorySize, PAIR_SMEM);

    k_prep<<<64, 256>>>(X, C);                       // 1
    k_wredM<<<1, 256>>>();                           // 2
    k_ya<<<NN/32, 256>>>(X, beta, a);                // 3
    k_pairs<<<NTILES, 256, PAIR_SMEM>>>(X, A);       // 4  <- profiled slot
    k_final<<<1, 256>>>(out);                        // 5
}

// round 9
// speedup vs baseline: 1.1903x; 1.0120x over previous
#include <cuda_runtime.h>
#include <math.h>
#include <stdint.h>

#define NN 8192
#define KK 32
#define NT 64                       // 8192/128 tiles per dim
#define NOFF (NT*(NT-1)/2)          // 2016 strictly-upper tiles
#define NTILES (NOFF + NT)          // 2080 partial slots

typedef unsigned long long u64;

#define FMA2(d,a,b,c) asm("fma.rn.f32x2 %0, %1, %2, %3;" : "=l"(d) : "l"(a), "l"(b), "l"(c))
#define PK2(d,lo,hi)  asm("mov.b64 %0, {%1, %2};" : "=l"(d) : "f"(lo), "f"(hi))
#define UPK2(lo,hi,s) asm("mov.b64 {%0, %1}, %2;" : "=f"(lo), "=f"(hi) : "l"(s))
#define CPA16(dst,src) asm volatile("cp.async.cg.shared.global [%0], [%1], 16;" :: "r"(dst), "l"(src))

// ---- scratch (no allocations allowed) ----
__device__ float  d_Wpart[64*KK*KK];    // partial Xs @ expC per 128-chunk
__device__ float  d_Spart[64*KK];       // partial column sums of expC
__device__ float  d_Ya  [KK*NN];        // 2a * M @ X
__device__ float  d_bv  [NN];           // beta - a*q
__device__ double d_partSP[NTILES];
__device__ double d_partTA[NTILES];

// ---------- fused prep: softmax(X) chunk + exp(C) chunk + partial W,S ----------
__global__ void k_prep(const float* __restrict__ X, const float* __restrict__ C) {
    __shared__ float xs[KK][132];
    __shared__ float ec[KK][132];
    int blk = blockIdx.x, tid = threadIdx.x;
    int base = blk * 128;

    if (tid < 128) {
        int i = base + tid;
        float v[KK]; float s = 0.f;
#pragma unroll
        for (int p = 0; p < KK; p++) { v[p] = __expf(X[p*NN + i]); s += v[p]; }
        float inv = 1.f / s;
#pragma unroll
        for (int p = 0; p < KK; p++) xs[p][tid] = v[p] * inv;
    } else {
        int r = tid - 128;
        const float4* cp = (const float4*)&C[(base + r)*KK];
#pragma unroll
        for (int c4 = 0; c4 < 8; c4++) {
            float4 v = cp[c4];
            ec[c4*4+0][r] = __expf(v.x);
            ec[c4*4+1][r] = __expf(v.y);
            ec[c4*4+2][r] = __expf(v.z);
            ec[c4*4+3][r] = __expf(v.w);
        }
    }
    __syncthreads();

    if (tid < 32) {
        float s = 0.f;
#pragma unroll 8
        for (int r = 0; r < 128; r++) s += ec[tid][r];
        d_Spart[blk*32 + tid] = s;
    }

    int p = tid >> 3, k0 = (tid & 7) * 4;
    float a0 = 0.f, a1 = 0.f, a2 = 0.f, a3 = 0.f;
#pragma unroll 4
    for (int ii = 0; ii < 128; ii++) {
        float xv = xs[p][ii];
        a0 += xv * ec[k0+0][ii];
        a1 += xv * ec[k0+1][ii];
        a2 += xv * ec[k0+2][ii];
        a3 += xv * ec[k0+3][ii];
    }
    float* out = &d_Wpart[blk*1024 + p*32 + k0];
    out[0] = a0; out[1] = a1; out[2] = a2; out[3] = a3;
}

// ---------- fused: (per-block redundant) W,S reduce -> M ; then Ya/bv for 64 cols ----------
__global__ void __launch_bounds__(256, 4)
k_yaM(const float* __restrict__ X, const float* __restrict__ beta,
      const float* __restrict__ a_p) {
    __shared__ float Es[KK*KK];
    __shared__ __align__(16) float Ms[KK][KK];
    __shared__ float Ssm[KK];
    __shared__ float Xw[KK][66];
    __shared__ float qsm[4][64];

    int tid = threadIdx.x;
    int cbase = blockIdx.x * 64;

    // stage X window first (independent DRAM loads, max MLP)
#pragma unroll
    for (int c = 0; c < 8; c++) {
        int idx = c*256 + tid;
        int q = idx >> 6, col = idx & 63;
        Xw[q][col] = X[q*NN + cbase + col];
    }

    // reduce Wpart (L2-resident after k_prep) and Spart
    float w[4];
#pragma unroll
    for (int c = 0; c < 4; c++) {
        int e = tid*4 + c;
        float s = 0.f;
#pragma unroll 8
        for (int b = 0; b < 64; b++) s += d_Wpart[b*1024 + e];
        w[c] = s;
    }
    if (tid < 32) {
        float s = 0.f;
#pragma unroll 8
        for (int b = 0; b < 64; b++) s += d_Spart[b*32 + tid];
        Ssm[tid] = s;
    }
    __syncthreads();
#pragma unroll
    for (int c = 0; c < 4; c++) {
        int e = tid*4 + c;
        Es[e] = w[c] / Ssm[e & 31];
    }
    __syncthreads();
#pragma unroll
    for (int c = 0; c < 4; c++) {
        int e = tid*4 + c;
        int p = e >> 5, q = e & 31;
        float s = 0.f;
#pragma unroll
        for (int r = 0; r < KK; r++) s += Es[r*KK + p] * Es[r*KK + q];
        Ms[p][q] = s;
    }
    __syncthreads();

    // Ya for 64 columns; thread: col = tid&63, p-group = tid>>6 (8 p's each)
    int col = tid & 63, pg = tid >> 6;
    float a = a_p[0];
    float twoa = 2.f * a;
    float xv[KK];
#pragma unroll
    for (int q = 0; q < KK; q++) xv[q] = Xw[q][col];

    int i = cbase + col;
    float qp = 0.f;
#pragma unroll
    for (int pp = 0; pp < 8; pp++) {
        int p = pg*8 + pp;
        const float4* mrow = (const float4*)&Ms[p][0];   // broadcast across 64 cols
        float tp = 0.f;
#pragma unroll
        for (int q4 = 0; q4 < 8; q4++) {
            float4 m = mrow[q4];
            tp += m.x * xv[q4*4+0] + m.y * xv[q4*4+1]
                + m.z * xv[q4*4+2] + m.w * xv[q4*4+3];
        }
        d_Ya[p*NN + i] = twoa * tp;     // coalesced per warp
        qp += xv[p] * tp;
    }
    qsm[pg][col] = qp;
    __syncthreads();
    if (pg == 0) {
        float qf = qsm[0][col] + qsm[1][col] + qsm[2][col] + qsm[3][col];
        d_bv[i] = beta[i] - a * qf;
    }
}

__device__ __forceinline__ float softplusf(float x) {
    return fmaxf(x, 0.f) + __logf(1.f + __expf(-fabsf(x)));
}

// ---------- off-diagonal tiles (I<J), 2016 blocks; dynamic smem (EXACT R4 core) ----------
// layout: Xt 16KB | Yt 16KB | Asm 64KB | bI 512B | bJ 512B | wSP 32B | wTA 32B
#define OFF_SMEM (16384 + 16384 + 65536 + 512 + 512 + 32 + 32)

__global__ void __launch_bounds__(256, 2)
k_pairs_off(const float* __restrict__ X, const float* __restrict__ A) {
    extern __shared__ char dynsm[];
    float (*Xt)[128]  = (float(*)[128])(dynsm);
    float (*Yt)[128]  = (float(*)[128])(dynsm + 16384);
    float (*Asm)[128] = (float(*)[128])(dynsm + 32768);
    float* bI  = (float*)(dynsm + 98304);
    float* bJ  = bI + 128;
    float* wSP = bJ + 128;
    float* wTA = wSP + 8;

    int t = blockIdx.x;
    int I = 0;
    { int rem = t, rl = NT - 1; while (rem >= rl) { rem -= rl; rl--; I++; } t = rem; }
    int J = I + 1 + t;
    int iBase = I * 128, jBase = J * 128;
    int tid = threadIdx.x;

    // stage the direct A block into smem via cp.async
    {
        uint32_t abase = (uint32_t)__cvta_generic_to_shared(&Asm[0][0]);
#pragma unroll
        for (int c = 0; c < 16; c++) {
            int idx = c*256 + tid;
            int row = idx >> 5, col16 = idx & 31;
            const float* src = &A[(u64)(iBase + row)*NN + jBase + col16*4];
            CPA16(abase + row*512 + col16*16, src);
        }
        asm volatile("cp.async.commit_group;");
    }

    // stage X/Ya tiles + biases
#pragma unroll
    for (int c = 0; c < 4; c++) {
        int e = c*1024 + tid*4;
        int p = e >> 7, ii = e & 127;
        *(float4*)&Xt[p][ii] = *(const float4*)&X   [p*NN + iBase + ii];
        *(float4*)&Yt[p][ii] = *(const float4*)&d_Ya[p*NN + jBase + ii];
    }
    if (tid < 128) bI[tid] = d_bv[iBase + tid];
    else           bJ[tid - 128] = d_bv[jBase + tid - 128];
    __syncthreads();

    int tx = tid & 15, ty = tid >> 4;
    float bIr[8], bJc[8];
#pragma unroll
    for (int r = 0; r < 8; r++) bIr[r] = bI[ty*8 + r];
#pragma unroll
    for (int c = 0; c < 4; c++) { bJc[c] = bJ[tx*4 + c]; bJc[c+4] = bJ[64 + tx*4 + c]; }

    u64 acc2[8][4];
#pragma unroll
    for (int r = 0; r < 8; r++)
#pragma unroll
        for (int cp = 0; cp < 4; cp++) {
            float lo = bIr[r] + bJc[2*cp];
            float hi = bIr[r] + bJc[2*cp + 1];
            PK2(acc2[r][cp], lo, hi);
        }

#pragma unroll
    for (int k = 0; k < KK; k++) {
        float4 xa = *(float4*)&Xt[k][ty*8];
        float4 xb = *(float4*)&Xt[k][ty*8 + 4];
        const u64* yp0 = (const u64*)&Yt[k][tx*4];
        const u64* yp1 = (const u64*)&Yt[k][64 + tx*4];
        u64 y2[4] = {yp0[0], yp0[1], yp1[0], yp1[1]};
        float xf[8] = {xa.x, xa.y, xa.z, xa.w, xb.x, xb.y, xb.z, xb.w};
#pragma unroll
        for (int r = 0; r < 8; r++) {
            u64 xx;
            PK2(xx, xf[r], xf[r]);
#pragma unroll
            for (int cp = 0; cp < 4; cp++)
                FMA2(acc2[r][cp], xx, y2[cp], acc2[r][cp]);
        }
    }
    // theta in acc2

    asm volatile("cp.async.wait_group 0;");
    __syncthreads();

    float sSP = 0.f, sTA = 0.f;
    u64 sTA2; PK2(sTA2, 0.f, 0.f);

    // transposed A block first (LDG burst)
#pragma unroll
    for (int c = 0; c < 8; c++) {
        int gj = jBase + ((c < 4) ? (tx*4 + c) : (64 + tx*4 + (c - 4)));
        float4 b0 = __ldcs((const float4*)&A[(u64)gj*NN + iBase + ty*8]);
        float4 b1 = __ldcs((const float4*)&A[(u64)gj*NN + iBase + ty*8 + 4]);
        float atv[8] = {b0.x, b0.y, b0.z, b0.w, b1.x, b1.y, b1.z, b1.w};
        int cp = c >> 1;
#pragma unroll
        for (int r = 0; r < 8; r++) {
            float t0, t1;
            UPK2(t0, t1, acc2[r][cp]);
            sTA += ((c & 1) ? t1 : t0) * atv[r];
        }
    }

    // direct A block from smem + softplus (MUFU interleaved with FMA)
#pragma unroll
    for (int r = 0; r < 8; r++) {
        int row = ty*8 + r;
        float4 a0 = *(const float4*)&Asm[row][tx*4];
        float4 a1 = *(const float4*)&Asm[row][64 + tx*4];
        u64 a2[4];
        PK2(a2[0], a0.x, a0.y); PK2(a2[1], a0.z, a0.w);
        PK2(a2[2], a1.x, a1.y); PK2(a2[3], a1.z, a1.w);
#pragma unroll
        for (int cp = 0; cp < 4; cp++) {
            float t0, t1;
            UPK2(t0, t1, acc2[r][cp]);
            sSP += softplusf(t0) + softplusf(t1);
            FMA2(sTA2, acc2[r][cp], a2[cp], sTA2);
        }
    }
    sSP *= 2.f;
    {
        float t0, t1;
        UPK2(t0, t1, sTA2);
        sTA += t0 + t1;
    }

#pragma unroll
    for (int o = 16; o > 0; o >>= 1) {
        sSP += __shfl_xor_sync(0xffffffffu, sSP, o);
        sTA += __shfl_xor_sync(0xffffffffu, sTA, o);
    }
    int wid = tid >> 5, lane = tid & 31;
    if (lane == 0) { wSP[wid] = sSP; wTA[wid] = sTA; }
    __syncthreads();
    if (tid == 0) {
        float s1 = 0.f, s2 = 0.f;
#pragma unroll
        for (int w = 0; w < 8; w++) { s1 += wSP[w]; s2 += wTA[w]; }
        d_partSP[blockIdx.x] = (double)s1;
        d_partTA[blockIdx.x] = (double)s2;
    }
}

// ---------- diagonal tiles (I==J), 64 blocks; static smem (EXACT R4) ----------
__global__ void __launch_bounds__(256, 2)
k_pairs_diag(const float* __restrict__ X, const float* __restrict__ A) {
    __shared__ float Xt[KK][128], Yt[KK][128], bI[128], bJ[128];
    __shared__ float wSP[8], wTA[8];
    int I = blockIdx.x;
    int iBase = I * 128, jBase = iBase;
    int tid = threadIdx.x;

#pragma unroll
    for (int c = 0; c < 4; c++) {
        int e = c*1024 + tid*4;
        int p = e >> 7, ii = e & 127;
        *(float4*)&Xt[p][ii] = *(const float4*)&X   [p*NN + iBase + ii];
        *(float4*)&Yt[p][ii] = *(const float4*)&d_Ya[p*NN + jBase + ii];
    }
    if (tid < 128) bI[tid] = d_bv[iBase + tid];
    else           bJ[tid - 128] = d_bv[jBase + tid - 128];
    __syncthreads();

    int tx = tid & 15, ty = tid >> 4;
    float bIr[8], bJc[8];
#pragma unroll
    for (int r = 0; r < 8; r++) bIr[r] = bI[ty*8 + r];
#pragma unroll
    for (int c = 0; c < 4; c++) { bJc[c] = bJ[tx*4 + c]; bJc[c+4] = bJ[64 + tx*4 + c]; }

    u64 acc2[8][4];
#pragma unroll
    for (int r = 0; r < 8; r++)
#pragma unroll
        for (int cp = 0; cp < 4; cp++)
            PK2(acc2[r][cp], bIr[r] + bJc[2*cp], bIr[r] + bJc[2*cp + 1]);

#pragma unroll
    for (int k = 0; k < KK; k++) {
        float4 xa = *(float4*)&Xt[k][ty*8];
        float4 xb = *(float4*)&Xt[k][ty*8 + 4];
        const u64* yp0 = (const u64*)&Yt[k][tx*4];
        const u64* yp1 = (const u64*)&Yt[k][64 + tx*4];
        u64 y2[4] = {yp0[0], yp0[1], yp1[0], yp1[1]};
        float xf[8] = {xa.x, xa.y, xa.z, xa.w, xb.x, xb.y, xb.z, xb.w};
#pragma unroll
        for (int r = 0; r < 8; r++) {
            u64 xx;
            PK2(xx, xf[r], xf[r]);
#pragma unroll
            for (int cp = 0; cp < 4; cp++)
                FMA2(acc2[r][cp], xx, y2[cp], acc2[r][cp]);
        }
    }

    float sSP = 0.f, sTA = 0.f;
#pragma unroll
    for (int r = 0; r < 8; r++) {
        int gi = iBase + ty*8 + r;
        float4 a0 = __ldcs((const float4*)&A[(u64)gi*NN + jBase + tx*4]);
        float4 a1 = __ldcs((const float4*)&A[(u64)gi*NN + jBase + 64 + tx*4]);
        float av[8] = {a0.x, a0.y, a0.z, a0.w, a1.x, a1.y, a1.z, a1.w};
#pragma unroll
        for (int c = 0; c < 8; c++) {
            int gj = jBase + ((c < 4) ? (tx*4 + c) : (64 + tx*4 + (c - 4)));
            float t0, t1;
            UPK2(t0, t1, acc2[r][c >> 1]);
            float th = (c & 1) ? t1 : t0;
            if (gi < gj) {
                sSP += 2.f * softplusf(th);
                sTA += th * av[c];
            } else if (gi == gj) {
                sTA += th * av[c];
            }
        }
    }
#pragma unroll
    for (int c = 0; c < 8; c++) {
        int gj = jBase + ((c < 4) ? (tx*4 + c) : (64 + tx*4 + (c - 4)));
        float4 b0 = __ldcs((const float4*)&A[(u64)gj*NN + iBase + ty*8]);
        float4 b1 = __ldcs((const float4*)&A[(u64)gj*NN + iBase + ty*8 + 4]);
        float atv[8] = {b0.x, b0.y, b0.z, b0.w, b1.x, b1.y, b1.z, b1.w};
#pragma unroll
        for (int r = 0; r < 8; r++) {
            int gi = iBase + ty*8 + r;
            float t0, t1;
            UPK2(t0, t1, acc2[r][c >> 1]);
            float th = (c & 1) ? t1 : t0;
            if (gi < gj) sTA += th * atv[r];
        }
    }

#pragma unroll
    for (int o = 16; o > 0; o >>= 1) {
        sSP += __shfl_xor_sync(0xffffffffu, sSP, o);
        sTA += __shfl_xor_sync(0xffffffffu, sTA, o);
    }
    int wid = tid >> 5, lane = tid & 31;
    if (lane == 0) { wSP[wid] = sSP; wTA[wid] = sTA; }
    __syncthreads();
    if (tid == 0) {
        float s1 = 0.f, s2 = 0.f;
#pragma unroll
        for (int w = 0; w < 8; w++) { s1 += wSP[w]; s2 += wTA[w]; }
        d_partSP[NOFF + I] = (double)s1;
        d_partTA[NOFF + I] = (double)s2;
    }
}

// ---------- deterministic final reduction ----------
__global__ void k_final(float* __restrict__ out) {
    __shared__ double rSP[256], rTA[256];
    int t = threadIdx.x;
    double s1 = 0.0, s2 = 0.0;
    for (int i = t; i < NTILES; i += 256) { s1 += d_partSP[i]; s2 += d_partTA[i]; }
    rSP[t] = s1; rTA[t] = s2; __syncthreads();
    for (int s = 128; s > 0; s >>= 1) {
        if (t < s) { rSP[t] += rSP[t+s]; rTA[t] += rTA[t+s]; }
        __syncthreads();
    }
    if (t == 0) out[0] = (float)(0.5 * rTA[0] - 0.5 * rSP[0]);
}

extern "C" void kernel_launch(void* const* d_in, const int* in_sizes, int n_in,
                              void* d_out, int out_size) {
    const float* A    = (const float*)d_in[0];
    const float* beta = (const float*)d_in[1];
    const float* a    = (const float*)d_in[2];
    const float* X    = (const float*)d_in[3];
    const float* C    = (const float*)d_in[4];
    float* out = (float*)d_out;

    cudaFuncSetAttribute(k_pairs_off, cudaFuncAttributeMaxDynamicSharedMemorySize, OFF_SMEM);

    k_prep<<<64, 256>>>(X, C);                       // 1
    k_yaM<<<NN/64, 256>>>(X, beta, a);               // 2 (fused wredM+M+ya)
    k_pairs_diag<<<NT, 256>>>(X, A);                 // 3
    k_pairs_off<<<NOFF, 256, OFF_SMEM>>>(X, A);      // 4  <- profiled slot
    k_final<<<1, 256>>>(out);                        // 5
}

// round 10
// speedup vs baseline: 1.1993x; 1.0076x over previous
#include <cuda_runtime.h>
#include <math.h>
#include <stdint.h>

#define NN 8192
#define KK 32
#define NT 64                       // 8192/128 tiles per dim
#define NOFF (NT*(NT-1)/2)          // 2016 strictly-upper tiles
#define NTILES (NOFF + NT)          // 2080 tiles (off + diag)

typedef unsigned long long u64;

#define FMA2(d,a,b,c) asm("fma.rn.f32x2 %0, %1, %2, %3;" : "=l"(d) : "l"(a), "l"(b), "l"(c))
#define PK2(d,lo,hi)  asm("mov.b64 %0, {%1, %2};" : "=l"(d) : "f"(lo), "f"(hi))
#define UPK2(lo,hi,s) asm("mov.b64 {%0, %1}, %2;" : "=f"(lo), "=f"(hi) : "l"(s))
#define CPA16(dst,src) asm volatile("cp.async.cg.shared.global [%0], [%1], 16;" :: "r"(dst), "l"(src))

// ---- scratch (no allocations allowed) ----
__device__ float  d_Wpart[64*KK*KK];    // partial Xs @ expC per 128-chunk
__device__ float  d_Spart[64*KK];       // partial column sums of expC
__device__ float  d_M [KK*KK];          // M = E^T E
__device__ float  d_Ya  [KK*NN];        // 2a * M @ X
__device__ float  d_bv  [NN];           // beta - a*q
__device__ double d_partSP[NTILES];
__device__ double d_partTA[NTILES];

// ---------- fused prep: softmax(X) chunk + exp(C) chunk + partial W,S ----------
__global__ void k_prep(const float* __restrict__ X, const float* __restrict__ C) {
    __shared__ float xs[KK][132];
    __shared__ float ec[KK][132];
    int blk = blockIdx.x, tid = threadIdx.x;
    int base = blk * 128;

    if (tid < 128) {
        int i = base + tid;
        float v[KK]; float s = 0.f;
#pragma unroll
        for (int p = 0; p < KK; p++) { v[p] = __expf(X[p*NN + i]); s += v[p]; }
        float inv = 1.f / s;
#pragma unroll
        for (int p = 0; p < KK; p++) xs[p][tid] = v[p] * inv;
    } else {
        int r = tid - 128;
        const float4* cp = (const float4*)&C[(base + r)*KK];
#pragma unroll
        for (int c4 = 0; c4 < 8; c4++) {
            float4 v = cp[c4];
            ec[c4*4+0][r] = __expf(v.x);
            ec[c4*4+1][r] = __expf(v.y);
            ec[c4*4+2][r] = __expf(v.z);
            ec[c4*4+3][r] = __expf(v.w);
        }
    }
    __syncthreads();

    if (tid < 32) {
        float s = 0.f;
#pragma unroll 8
        for (int r = 0; r < 128; r++) s += ec[tid][r];
        d_Spart[blk*32 + tid] = s;
    }

    int p = tid >> 3, k0 = (tid & 7) * 4;
    float a0 = 0.f, a1 = 0.f, a2 = 0.f, a3 = 0.f;
#pragma unroll 4
    for (int ii = 0; ii < 128; ii++) {
        float xv = xs[p][ii];
        a0 += xv * ec[k0+0][ii];
        a1 += xv * ec[k0+1][ii];
        a2 += xv * ec[k0+2][ii];
        a3 += xv * ec[k0+3][ii];
    }
    float* out = &d_Wpart[blk*1024 + p*32 + k0];
    out[0] = a0; out[1] = a1; out[2] = a2; out[3] = a3;
}

// ---------- reduce partials, E = W/S, M = E^T E (one block) ----------
__global__ void k_wredM() {
    __shared__ float Es[KK*KK];
    __shared__ float Ssm[KK];
    int tid = threadIdx.x;
    float w[4];
#pragma unroll
    for (int c = 0; c < 4; c++) {
        int e = tid*4 + c;
        float s = 0.f;
#pragma unroll 8
        for (int b = 0; b < 64; b++) s += d_Wpart[b*1024 + e];
        w[c] = s;
    }
    if (tid < 32) {
        float s = 0.f;
#pragma unroll 8
        for (int b = 0; b < 64; b++) s += d_Spart[b*32 + tid];
        Ssm[tid] = s;
    }
    __syncthreads();
#pragma unroll
    for (int c = 0; c < 4; c++) {
        int e = tid*4 + c;
        Es[e] = w[c] / Ssm[e & 31];
    }
    __syncthreads();
#pragma unroll
    for (int c = 0; c < 4; c++) {
        int e = tid*4 + c;
        int p = e >> 5, q = e & 31;
        float s = 0.f;
#pragma unroll
        for (int r = 0; r < KK; r++) s += Es[r*KK + p] * Es[r*KK + q];
        d_M[e] = s;
    }
}

// ---------- Ya = 2a*M*X, b = beta - a*q (64 cols/block, no reg cap) ----------
__global__ void k_ya(const float* __restrict__ X, const float* __restrict__ beta,
                     const float* __restrict__ a_p) {
    __shared__ __align__(16) float Ms[KK][KK];
    __shared__ float Xw[KK][66];
    __shared__ float qsm[4][64];
    int tid = threadIdx.x;
    int cbase = blockIdx.x * 64;

    // stage X window first (independent DRAM loads, max MLP)
#pragma unroll
    for (int c = 0; c < 8; c++) {
        int idx = c*256 + tid;
        int q = idx >> 6, col = idx & 63;
        Xw[q][col] = X[q*NN + cbase + col];
    }
#pragma unroll
    for (int c = 0; c < 4; c++) {
        int idx = c*256 + tid;
        Ms[idx >> 5][idx & 31] = d_M[idx];
    }
    __syncthreads();

    int col = tid & 63, pg = tid >> 6;
    float a = a_p[0];
    float twoa = 2.f * a;
    float xv[KK];
#pragma unroll
    for (int q = 0; q < KK; q++) xv[q] = Xw[q][col];

    int i = cbase + col;
    float qp = 0.f;
#pragma unroll
    for (int pp = 0; pp < 8; pp++) {
        int p = pg*8 + pp;
        const float4* mrow = (const float4*)&Ms[p][0];   // broadcast
        float tp = 0.f;
#pragma unroll
        for (int q4 = 0; q4 < 8; q4++) {
            float4 m = mrow[q4];
            tp += m.x * xv[q4*4+0] + m.y * xv[q4*4+1]
                + m.z * xv[q4*4+2] + m.w * xv[q4*4+3];
        }
        d_Ya[p*NN + i] = twoa * tp;     // coalesced per warp-half
        qp += xv[p] * tp;
    }
    qsm[pg][col] = qp;
    __syncthreads();
    if (pg == 0) {
        float qf = qsm[0][col] + qsm[1][col] + qsm[2][col] + qsm[3][col];
        d_bv[i] = beta[i] - a * qf;
    }
}

__device__ __forceinline__ float softplusf(float x) {
    return fmaxf(x, 0.f) + __logf(1.f + __expf(-fabsf(x)));
}

// ---------- unified pair kernel: 2080 tiles, R4 core + diag branch ----------
// layout: Xt 16KB | Yt 16KB | Asm 64KB | bI 512B | bJ 512B | wSP 32B | wTA 32B
#define OFF_SMEM (16384 + 16384 + 65536 + 512 + 512 + 32 + 32)

__global__ void __launch_bounds__(256, 2)
k_pairs(const float* __restrict__ X, const float* __restrict__ A) {
    extern __shared__ char dynsm[];
    float (*Xt)[128]  = (float(*)[128])(dynsm);
    float (*Yt)[128]  = (float(*)[128])(dynsm + 16384);
    float (*Asm)[128] = (float(*)[128])(dynsm + 32768);
    float* bI  = (float*)(dynsm + 98304);
    float* bJ  = bI + 128;
    float* wSP = bJ + 128;
    float* wTA = wSP + 8;

    int pid = blockIdx.x, tid = threadIdx.x;
    int I, J;
    if (pid < NOFF) {
        int rem = pid, rl = NT - 1; I = 0;
        while (rem >= rl) { rem -= rl; rl--; I++; }
        J = I + 1 + rem;
    } else {
        I = pid - NOFF; J = I;
    }
    bool isDiag = (I == J);
    int iBase = I * 128, jBase = J * 128;

    // stage the direct A block into smem via cp.async (overlaps mainloop)
    {
        uint32_t abase = (uint32_t)__cvta_generic_to_shared(&Asm[0][0]);
#pragma unroll
        for (int c = 0; c < 16; c++) {
            int idx = c*256 + tid;
            int row = idx >> 5, col16 = idx & 31;
            const float* src = &A[(u64)(iBase + row)*NN + jBase + col16*4];
            CPA16(abase + row*512 + col16*16, src);
        }
        asm volatile("cp.async.commit_group;");
    }

    // stage X/Ya tiles + biases
#pragma unroll
    for (int c = 0; c < 4; c++) {
        int e = c*1024 + tid*4;
        int p = e >> 7, ii = e & 127;
        *(float4*)&Xt[p][ii] = *(const float4*)&X   [p*NN + iBase + ii];
        *(float4*)&Yt[p][ii] = *(const float4*)&d_Ya[p*NN + jBase + ii];
    }
    if (tid < 128) bI[tid] = d_bv[iBase + tid];
    else           bJ[tid - 128] = d_bv[jBase + tid - 128];
    __syncthreads();

    int tx = tid & 15, ty = tid >> 4;
    float bIr[8], bJc[8];
#pragma unroll
    for (int r = 0; r < 8; r++) bIr[r] = bI[ty*8 + r];
#pragma unroll
    for (int c = 0; c < 4; c++) { bJc[c] = bJ[tx*4 + c]; bJc[c+4] = bJ[64 + tx*4 + c]; }

    u64 acc2[8][4];
#pragma unroll
    for (int r = 0; r < 8; r++)
#pragma unroll
        for (int cp = 0; cp < 4; cp++) {
            float lo = bIr[r] + bJc[2*cp];
            float hi = bIr[r] + bJc[2*cp + 1];
            PK2(acc2[r][cp], lo, hi);
        }

    // FFMA2 mainloop (dir A-stream arrives underneath)
#pragma unroll
    for (int k = 0; k < KK; k++) {
        float4 xa = *(float4*)&Xt[k][ty*8];
        float4 xb = *(float4*)&Xt[k][ty*8 + 4];
        const u64* yp0 = (const u64*)&Yt[k][tx*4];
        const u64* yp1 = (const u64*)&Yt[k][64 + tx*4];
        u64 y2[4] = {yp0[0], yp0[1], yp1[0], yp1[1]};
        float xf[8] = {xa.x, xa.y, xa.z, xa.w, xb.x, xb.y, xb.z, xb.w};
#pragma unroll
        for (int r = 0; r < 8; r++) {
            u64 xx;
            PK2(xx, xf[r], xf[r]);
#pragma unroll
            for (int cp = 0; cp < 4; cp++)
                FMA2(acc2[r][cp], xx, y2[cp], acc2[r][cp]);
        }
    }
    // theta in acc2

    asm volatile("cp.async.wait_group 0;");
    __syncthreads();

    float sSP = 0.f, sTA = 0.f;
    u64 sTA2; PK2(sTA2, 0.f, 0.f);

    if (!isDiag) {
        // transposed A block first (LDG burst)
#pragma unroll
        for (int c = 0; c < 8; c++) {
            int gj = jBase + ((c < 4) ? (tx*4 + c) : (64 + tx*4 + (c - 4)));
            float4 b0 = __ldcs((const float4*)&A[(u64)gj*NN + iBase + ty*8]);
            float4 b1 = __ldcs((const float4*)&A[(u64)gj*NN + iBase + ty*8 + 4]);
            float atv[8] = {b0.x, b0.y, b0.z, b0.w, b1.x, b1.y, b1.z, b1.w};
            int cp = c >> 1;
#pragma unroll
            for (int r = 0; r < 8; r++) {
                float t0, t1;
                UPK2(t0, t1, acc2[r][cp]);
                sTA += ((c & 1) ? t1 : t0) * atv[r];
            }
        }

        // direct A block from smem + softplus (MUFU interleaved with FMA)
#pragma unroll
        for (int r = 0; r < 8; r++) {
            int row = ty*8 + r;
            float4 a0 = *(const float4*)&Asm[row][tx*4];
            float4 a1 = *(const float4*)&Asm[row][64 + tx*4];
            u64 a2[4];
            PK2(a2[0], a0.x, a0.y); PK2(a2[1], a0.z, a0.w);
            PK2(a2[2], a1.x, a1.y); PK2(a2[3], a1.z, a1.w);
#pragma unroll
            for (int cp = 0; cp < 4; cp++) {
                float t0, t1;
                UPK2(t0, t1, acc2[r][cp]);
                sSP += softplusf(t0) + softplusf(t1);
                FMA2(sTA2, acc2[r][cp], a2[cp], sTA2);
            }
        }
        sSP *= 2.f;
    } else {
        // diag tile: full dir-block theta.A sum (theta symmetric => counts
        // each i<j pair once with A_ij+A_ji, plus the i==j terms), masked softplus.
#pragma unroll
        for (int r = 0; r < 8; r++) {
            int row = ty*8 + r;
            float4 a0 = *(const float4*)&Asm[row][tx*4];
            float4 a1 = *(const float4*)&Asm[row][64 + tx*4];
            u64 a2[4];
            PK2(a2[0], a0.x, a0.y); PK2(a2[1], a0.z, a0.w);
            PK2(a2[2], a1.x, a1.y); PK2(a2[3], a1.z, a1.w);
#pragma unroll
            for (int cp = 0; cp < 4; cp++)
                FMA2(sTA2, acc2[r][cp], a2[cp], sTA2);
#pragma unroll
            for (int c = 0; c < 8; c++) {
                int colL = (c < 4) ? (tx*4 + c) : (64 + tx*4 + (c - 4));
                float t0, t1;
                UPK2(t0, t1, acc2[r][c >> 1]);
                float th = (c & 1) ? t1 : t0;
                if (row < colL) sSP += 2.f * softplusf(th);
            }
        }
    }
    {
        float t0, t1;
        UPK2(t0, t1, sTA2);
        sTA += t0 + t1;
    }

    // deterministic block reduction
#pragma unroll
    for (int o = 16; o > 0; o >>= 1) {
        sSP += __shfl_xor_sync(0xffffffffu, sSP, o);
        sTA += __shfl_xor_sync(0xffffffffu, sTA, o);
    }
    int wid = tid >> 5, lane = tid & 31;
    if (lane == 0) { wSP[wid] = sSP; wTA[wid] = sTA; }
    __syncthreads();
    if (tid == 0) {
        float s1 = 0.f, s2 = 0.f;
#pragma unroll
        for (int w = 0; w < 8; w++) { s1 += wSP[w]; s2 += wTA[w]; }
        d_partSP[pid] = (double)s1;
        d_partTA[pid] = (double)s2;
    }
}

// ---------- deterministic final reduction ----------
__global__ void k_final(float* __restrict__ out) {
    __shared__ double rSP[256], rTA[256];
    int t = threadIdx.x;
    double s1 = 0.0, s2 = 0.0;
    for (int i = t; i < NTILES; i += 256) { s1 += d_partSP[i]; s2 += d_partTA[i]; }
    rSP[t] = s1; rTA[t] = s2; __syncthreads();
    for (int s = 128; s > 0; s >>= 1) {
        if (t < s) { rSP[t] += rSP[t+s]; rTA[t] += rTA[t+s]; }
        __syncthreads();
    }
    if (t == 0) out[0] = (float)(0.5 * rTA[0] - 0.5 * rSP[0]);
}

extern "C" void kernel_launch(void* const* d_in, const int* in_sizes, int n_in,
                              void* d_out, int out_size) {
    const float* A    = (const float*)d_in[0];
    const float* beta = (const float*)d_in[1];
    const float* a    = (const float*)d_in[2];
    const float* X    = (const float*)d_in[3];
    const float* C    = (const float*)d_in[4];
    float* out = (float*)d_out;

    cudaFuncSetAttribute(k_pairs, cudaFuncAttributeMaxDynamicSharedMemorySize, OFF_SMEM);

    k_prep<<<64, 256>>>(X, C);                       // 1
    k_wredM<<<1, 256>>>();                           // 2
    k_ya<<<NN/64, 256>>>(X, beta, a);                // 3
    k_pairs<<<NTILES, 256, OFF_SMEM>>>(X, A);        // 4  <- profiled slot
    k_final<<<1, 256>>>(out);                        // 5
}